// round 3
// baseline (speedup 1.0000x reference)
#include <cuda_runtime.h>
#include <math_constants.h>

// Problem constants (fixed by the dataset)
#define B_      128
#define L_I     2
#define L_Q     10
#define N_ACT   8
#define IM      64
#define IMP     66
#define NPIX    4096
#define NTHR    256
#define TILES   8
#define ROWS    8          // output rows per CTA (fast path)
#define INROWS  12         // ROWS + 4 halo input rows

#define Q_ELEMS   (B_ * L_Q * NPIX)       // 5242880
#define LOGIT_OFF Q_ELEMS
#define ACT_OFF   (Q_ELEMS + B_ * N_ACT)  // 5243904

// grid-wide argmax state (self-resetting each launch -> graph-replay safe)
__device__ unsigned long long g_best  = 0ULL;
__device__ unsigned int       g_count = 0u;

// slow-path (w != 0) scratch — never touched on the fast path
__device__ float g_r  [B_][IMP * IMP];          // ~2.2 MB
__device__ float g_qr [B_][L_Q][NPIX];          // ~21 MB
__device__ float g_vb [2][B_][IMP * IMP];       // ~4.5 MB

__device__ __forceinline__ unsigned int ordered_f32(float f) {
    unsigned int u = __float_as_uint(f);
    return (u & 0x80000000u) ? ~u : (u | 0x80000000u);
}

// logits from qv[10], write to out, contribute to grid argmax. One thread calls.
__device__ __forceinline__ void logits_and_argmax(const float* qv, const float* fc_s,
                                                  float* out, int b) {
    float best = -CUDART_INF_F;
    int   bi   = 0;
    #pragma unroll
    for (int a = 0; a < N_ACT; a++) {
        float s = 0.f;
        #pragma unroll
        for (int o = 0; o < L_Q; o++) s += fc_s[a * L_Q + o] * qv[o];
        out[LOGIT_OFF + b * N_ACT + a] = s;
        if (s > best) { best = s; bi = b * N_ACT + a; }   // strict > keeps first
    }
    const unsigned long long key =
        ((unsigned long long)ordered_f32(best) << 32) |
        (unsigned long long)(0xFFFFFFFFu - (unsigned int)bi);
    atomicMax(&g_best, key);
    __threadfence();
    const unsigned int cnt = atomicAdd(&g_count, 1u);
    if (cnt == B_ - 1u) {                 // exactly B_ contributors grid-wide
        const unsigned long long k2 = atomicMax(&g_best, 0ULL);   // atomic read
        const unsigned int flat = 0xFFFFFFFFu - (unsigned int)(k2 & 0xFFFFFFFFu);
        out[ACT_OFF] = (float)flat;
        g_best = 0ULL;                    // reset for next graph replay
        __threadfence();
        atomicExch(&g_count, 0u);
    }
}

__global__ __launch_bounds__(NTHR, 4)
void vin_kernel(const float* __restrict__ in,
                const int*   __restrict__ sx_,
                const int*   __restrict__ sy_,
                const int*   __restrict__ kptr,   // may be null
                const float* __restrict__ h_w,
                const float* __restrict__ h_b,
                const float* __restrict__ r_w,
                const float* __restrict__ q_w,
                const float* __restrict__ w,
                const float* __restrict__ fc_w,
                float* __restrict__ out)
{
    __shared__ float in_s[L_I][INROWS][IMP];   // zero col-halo, rows gx0-2..gx0+9
    __shared__ float r_s[ROWS + 2][IMP];       // rows gx0-1..gx0+8, zero halo
    __shared__ float weff[18];
    __shared__ float qw_s[90];
    __shared__ float ww_s[90];
    __shared__ float fc_s[80];
    __shared__ float beff_s;

    const int tile = blockIdx.x;
    const int b    = blockIdx.y;
    const int gx0  = tile * ROWS;
    const int tid  = threadIdx.x;

    // ---------------- phase 0: zero smem that needs it ----------------
    for (int i = tid; i < (ROWS + 2) * IMP; i += NTHR) ((float*)r_s)[i] = 0.f;
    if (tid < 48) {  // in_s column halos
        const int i = tid / 24, rr = (tid % 24) >> 1, c = (tid & 1) * (IMP - 1);
        in_s[i][rr][c] = 0.f;
    }

    // ---------------- phase 1: stage input tile (coalesced) ----------------
    {
        const float* inb = in + (size_t)b * L_I * NPIX;
        for (int e = tid; e < L_I * INROWS * IM; e += NTHR) {
            const int ch  = (e >= INROWS * IM);
            const int rem = e - ch * (INROWS * IM);
            const int row = rem >> 6, col = rem & 63;
            const int gr  = gx0 - 2 + row;
            in_s[ch][row][col + 1] =
                (gr >= 0 && gr < IM) ? inb[ch * NPIX + gr * IM + col] : 0.f;
        }
    }

    // ---------------- phase 1b: weight collapse (warps 0-4) + small loads --------
    // weff[i*9+t] = sum_c r_w[c] * h_w[(c*2+i)*9+t] ; beff = sum_c r_w[c]*h_b[c]
    if (tid < 160) {             // warps 0..4 fully active -> full-mask shuffles OK
        const int item = tid >> 3;       // 0..19 (19 -> dummy)
        const int l    = tid & 7;
        float acc = 0.f;
        if (item < 18) {
            const int i = item / 9, t = item % 9;
            for (int c = l; c < 150; c += 8)
                acc += r_w[c] * h_w[(c * L_I + i) * 9 + t];
        } else if (item == 18) {
            for (int c = l; c < 150; c += 8)
                acc += r_w[c] * h_b[c];
        }
        acc += __shfl_xor_sync(0xFFFFFFFFu, acc, 4);
        acc += __shfl_xor_sync(0xFFFFFFFFu, acc, 2);
        acc += __shfl_xor_sync(0xFFFFFFFFu, acc, 1);
        if (l == 0) {
            if (item < 18)       weff[item] = acc;
            else if (item == 18) beff_s = acc;
        }
    } else if (tid < 250) {      // warps 5-7: stage the small weight tensors
        const int j = tid - 160;     // 0..89
        qw_s[j] = q_w[j];
        ww_s[j] = w[j];
        if (j < 80) fc_s[j] = fc_w[j];
    }
    __syncthreads();

    // ---------------- phase 2: r = conv3x3(input, weff) + beff (branchless taps) --
    {
        const float be = beff_s;
        for (int e = tid; e < (ROWS + 2) * IM; e += NTHR) {
            const int rx = e >> 6, y = e & 63;
            const int gr = gx0 - 1 + rx;
            if (gr >= 0 && gr < IM) {
                float acc = be;
                #pragma unroll
                for (int i = 0; i < L_I; i++)
                    #pragma unroll
                    for (int kh = 0; kh < 3; kh++)
                        #pragma unroll
                        for (int kw = 0; kw < 3; kw++)
                            acc += in_s[i][rx + kh][y + kw] * weff[i * 9 + kh * 3 + kw];
                r_s[rx][y + 1] = acc;
            }
        }
    }
    const int nz = (tid < 90) ? (ww_s[tid] != 0.f) : 0;
    const int f  = __syncthreads_or(nz);   // barrier: r_s ready, flag uniform

    float* outb = out + (size_t)b * L_Q * NPIX;

    if (!f) {
        // ================== FAST PATH: w == 0 -> q == conv(r, q_w) ==================
        const int y   = tid & 63;
        const int ox0 = tid >> 6;        // rows 0..3
        const int ox1 = ox0 + 4;         // rows 4..7
        float t0[9], t1[9];
        #pragma unroll
        for (int kh = 0; kh < 3; kh++)
            #pragma unroll
            for (int kw = 0; kw < 3; kw++) {
                t0[kh * 3 + kw] = r_s[ox0 + kh][y + kw];
                t1[kh * 3 + kw] = r_s[ox1 + kh][y + kw];
            }
        #pragma unroll 1
        for (int o = 0; o < L_Q; o++) {
            float q0 = 0.f, q1 = 0.f;
            #pragma unroll
            for (int j = 0; j < 9; j++) {
                const float wv = qw_s[o * 9 + j];
                q0 += t0[j] * wv;
                q1 += t1[j] * wv;
            }
            outb[o * NPIX + (gx0 + ox0) * IM + y] = q0;
            outb[o * NPIX + (gx0 + ox1) * IM + y] = q1;
        }
        // gather + logits + argmax: only the CTA whose rows contain sx
        if (tid == 0) {
            const int sx = sx_[b];
            if (sx >= gx0 && sx < gx0 + ROWS) {
                const int sy = sy_[b];
                float qv[L_Q];
                #pragma unroll
                for (int o = 0; o < L_Q; o++) {
                    float a = 0.f;
                    #pragma unroll
                    for (int kh = 0; kh < 3; kh++)
                        #pragma unroll
                        for (int kw = 0; kw < 3; kw++)
                            a += r_s[sx - gx0 + kh][sy + kw] * qw_s[o * 9 + kh * 3 + kw];
                    qv[o] = a;
                }
                logits_and_argmax(qv, fc_s, out, b);
            }
        }
        return;
    }

    // ================== SLOW PATH: w != 0, full k-iteration (tile 0 only) ==========
    if (tile != 0) return;
    {
        const int kk = (kptr != nullptr) ? *kptr : 40;
        const float be = beff_s;
        const float* inb = in + (size_t)b * L_I * NPIX;

        for (int i = tid; i < IMP * IMP; i += NTHR) {
            g_r[b][i] = 0.f; g_vb[0][b][i] = 0.f; g_vb[1][b][i] = 0.f;
        }
        __syncthreads();

        // full-image r
        for (int e = tid; e < NPIX; e += NTHR) {
            const int x = e >> 6, y = e & 63;
            float acc = be;
            for (int i = 0; i < L_I; i++)
                for (int kh = 0; kh < 3; kh++) {
                    const int ix = x + kh - 1;
                    if (ix < 0 || ix >= IM) continue;
                    for (int kw = 0; kw < 3; kw++) {
                        const int iy = y + kw - 1;
                        if (iy < 0 || iy >= IM) continue;
                        acc += inb[i * NPIX + ix * IM + iy] * weff[i * 9 + kh * 3 + kw];
                    }
                }
            g_r[b][(x + 1) * IMP + y + 1] = acc;
        }
        __syncthreads();

        // qr + v0
        for (int e = tid; e < NPIX; e += NTHR) {
            const int x = e >> 6, y = e & 63;
            float t[9];
            for (int kh = 0; kh < 3; kh++)
                for (int kw = 0; kw < 3; kw++)
                    t[kh * 3 + kw] = g_r[b][(x + kh) * IMP + y + kw];
            float vmax = -CUDART_INF_F;
            for (int o = 0; o < L_Q; o++) {
                float a = 0.f;
                for (int j = 0; j < 9; j++) a += t[j] * qw_s[o * 9 + j];
                g_qr[b][o][e] = a;
                vmax = fmaxf(vmax, a);
            }
            g_vb[0][b][(x + 1) * IMP + y + 1] = vmax;
        }
        __syncthreads();

        int cur = 0;
        for (int it = 0; it < kk - 1; it++) {
            for (int e = tid; e < NPIX; e += NTHR) {
                const int x = e >> 6, y = e & 63;
                float t[9];
                for (int kh = 0; kh < 3; kh++)
                    for (int kw = 0; kw < 3; kw++)
                        t[kh * 3 + kw] = g_vb[cur][b][(x + kh) * IMP + y + kw];
                float vmax = -CUDART_INF_F;
                for (int o = 0; o < L_Q; o++) {
                    float a = g_qr[b][o][e];
                    for (int j = 0; j < 9; j++) a += t[j] * ww_s[o * 9 + j];
                    vmax = fmaxf(vmax, a);
                }
                g_vb[cur ^ 1][b][(x + 1) * IMP + y + 1] = vmax;
            }
            cur ^= 1;
            __syncthreads();
        }

        // final q = qr + conv(v, w)
        for (int e = tid; e < NPIX; e += NTHR) {
            const int x = e >> 6, y = e & 63;
            float t[9];
            for (int kh = 0; kh < 3; kh++)
                for (int kw = 0; kw < 3; kw++)
                    t[kh * 3 + kw] = g_vb[cur][b][(x + kh) * IMP + y + kw];
            for (int o = 0; o < L_Q; o++) {
                float a = g_qr[b][o][e];
                for (int j = 0; j < 9; j++) a += t[j] * ww_s[o * 9 + j];
                outb[o * NPIX + e] = a;
            }
        }
        __syncthreads();

        if (tid == 0) {
            const int sx = sx_[b], sy = sy_[b];
            float qv[L_Q];
            for (int o = 0; o < L_Q; o++) {
                float a = g_qr[b][o][sx * IM + sy];
                for (int kh = 0; kh < 3; kh++)
                    for (int kw = 0; kw < 3; kw++)
                        a += g_vb[cur][b][(sx + kh) * IMP + sy + kw] * ww_s[o * 9 + kh * 3 + kw];
                qv[o] = a;
            }
            logits_and_argmax(qv, fc_s, out, b);
        }
    }
}

extern "C" void kernel_launch(void* const* d_in, const int* in_sizes, int n_in,
                              void* d_out, int out_size)
{
    // Inputs: input_view, state_x, state_y, [k], h_w, h_b, r_w, q_w, w, fc_w
    int hw_idx = -1;
    for (int i = 0; i < n_in; i++) {
        if (in_sizes[i] == 2700) { hw_idx = i; break; }
    }
    if (hw_idx < 0) hw_idx = 4;

    const float* in_v = (const float*)d_in[0];
    const int*   sx   = (const int*)d_in[1];
    const int*   sy   = (const int*)d_in[2];
    const int*   kptr = (hw_idx == 4) ? (const int*)d_in[3] : nullptr;
    const float* h_w  = (const float*)d_in[hw_idx];
    const float* h_b  = (const float*)d_in[hw_idx + 1];
    const float* r_w  = (const float*)d_in[hw_idx + 2];
    const float* q_w  = (const float*)d_in[hw_idx + 3];
    const float* w    = (const float*)d_in[hw_idx + 4];
    const float* fc_w = (const float*)d_in[hw_idx + 5];
    float* out = (float*)d_out;

    dim3 grid(TILES, B_);
    vin_kernel<<<grid, NTHR>>>(in_v, sx, sy, kptr, h_w, h_b, r_w,
                               q_w, w, fc_w, out);
}

// round 4
// speedup vs baseline: 1.4510x; 1.4510x over previous
#include <cuda_runtime.h>
#include <math_constants.h>

// Problem constants (fixed by the dataset)
#define B_      128
#define L_I     2
#define L_Q     10
#define N_ACT   8
#define IM      64
#define IMP     66
#define NPIX    4096
#define NTHR    256
#define TILE    16         // output rows per CTA (fast path)
#define TILES   4
#define INROWS  20         // TILE + 4 halo input rows
#define RROWS   18         // TILE + 2 halo r rows
#define STRIDE  68         // padded row stride (floats), keeps float2 8B-aligned

#define Q_ELEMS   (B_ * L_Q * NPIX)       // 5242880
#define LOGIT_OFF Q_ELEMS
#define ACT_OFF   (Q_ELEMS + B_ * N_ACT)  // 5243904

// grid-wide argmax state (self-resetting each launch -> graph-replay safe)
__device__ unsigned long long g_best  = 0ULL;
__device__ unsigned int       g_count = 0u;

// slow-path (w != 0) scratch — never touched on the fast path
__device__ float g_r  [B_][IMP * IMP];
__device__ float g_qr [B_][L_Q][NPIX];
__device__ float g_vb [2][B_][IMP * IMP];

typedef unsigned long long ull;
__device__ __forceinline__ ull pk2(float x, float y) {
    ull r; asm("mov.b64 %0,{%1,%2};" : "=l"(r) : "f"(x), "f"(y)); return r;
}
__device__ __forceinline__ ull f2u(float2 v) {
    ull r; asm("mov.b64 %0,{%1,%2};" : "=l"(r) : "f"(v.x), "f"(v.y)); return r;
}
__device__ __forceinline__ float2 u2f(ull u) {
    float2 v; asm("mov.b64 {%0,%1},%2;" : "=f"(v.x), "=f"(v.y) : "l"(u)); return v;
}
__device__ __forceinline__ ull ffma2(ull a, ull b, ull c) {
    ull d; asm("fma.rn.f32x2 %0,%1,%2,%3;" : "=l"(d) : "l"(a), "l"(b), "l"(c)); return d;
}

__device__ __forceinline__ unsigned int ordered_f32(float f) {
    unsigned int u = __float_as_uint(f);
    return (u & 0x80000000u) ? ~u : (u | 0x80000000u);
}

// logits from qv[10], write to out, contribute to grid argmax. One thread calls.
__device__ __forceinline__ void logits_and_argmax(const float* qv, const float* fc_s,
                                                  float* out, int b) {
    float best = -CUDART_INF_F;
    int   bi   = 0;
    #pragma unroll
    for (int a = 0; a < N_ACT; a++) {
        float s = 0.f;
        #pragma unroll
        for (int o = 0; o < L_Q; o++) s += fc_s[a * L_Q + o] * qv[o];
        out[LOGIT_OFF + b * N_ACT + a] = s;
        if (s > best) { best = s; bi = b * N_ACT + a; }   // strict > keeps first
    }
    const unsigned long long key =
        ((unsigned long long)ordered_f32(best) << 32) |
        (unsigned long long)(0xFFFFFFFFu - (unsigned int)bi);
    atomicMax(&g_best, key);
    __threadfence();
    const unsigned int cnt = atomicAdd(&g_count, 1u);
    if (cnt == B_ - 1u) {                 // exactly B_ contributors grid-wide
        const unsigned long long k2 = atomicMax(&g_best, 0ULL);   // atomic read
        const unsigned int flat = 0xFFFFFFFFu - (unsigned int)(k2 & 0xFFFFFFFFu);
        out[ACT_OFF] = (float)flat;
        g_best = 0ULL;
        __threadfence();
        atomicExch(&g_count, 0u);
    }
}

__global__ __launch_bounds__(NTHR, 3)
void vin_kernel(const float* __restrict__ in,
                const int*   __restrict__ sx_,
                const int*   __restrict__ sy_,
                const int*   __restrict__ kptr,   // may be null
                const float* __restrict__ h_w,
                const float* __restrict__ h_b,
                const float* __restrict__ r_w,
                const float* __restrict__ q_w,
                const float* __restrict__ w,
                const float* __restrict__ fc_w,
                float* __restrict__ out)
{
    __shared__ float  in_s[L_I][INROWS][STRIDE];  // input tile, left pad 1, zero halos
    __shared__ float  uni[3000];   // transient: h_w[2700]+r_w[150]+h_b[150]; later r_s[18*68]
    __shared__ float2 qw2[90];     // q_w replicated (w,w) for FFMA2
    __shared__ float  ww_s[90];
    __shared__ float  fc_s[80];
    __shared__ float  weffb[19];   // [0..17]=weff, [18]=beff

    float* r_s  = uni;             // [RROWS][STRIDE], aliases dead h_w staging
    float* rw_s = uni + 2700;
    float* hb_s = uni + 2850;

    const int tile = blockIdx.x;
    const int b    = blockIdx.y;
    const int gx0  = tile * TILE;
    const int tid  = threadIdx.x;

    // ================= phase A: stage everything, coalesced, max MLP =================
    {
        const float* inb = in + (size_t)b * L_I * NPIX;
        #pragma unroll
        for (int i = 0; i < (L_I * INROWS * IM) / NTHR; i++) {   // 10
            const int e   = tid + i * NTHR;
            const int ch  = e >= (INROWS * IM);
            const int rem = e - ch * (INROWS * IM);
            const int row = rem >> 6, col = rem & 63;
            const int gr  = gx0 - 2 + row;
            in_s[ch][row][col + 1] =
                (gr >= 0 && gr < IM) ? inb[ch * NPIX + gr * IM + col] : 0.f;
        }
    }
    if (tid < 80) {   // in_s column halos (idx 0 and 65)
        const int ch = tid / 40, rr = (tid % 40) >> 1, c = (tid & 1) * 65;
        in_s[ch][rr][c] = 0.f;
    }
    #pragma unroll
    for (int i = 0; i < 11; i++) {
        const int e = tid + i * NTHR;
        if (e < 2700) uni[e] = h_w[e];
    }
    if (tid < 150) { rw_s[tid] = r_w[tid]; hb_s[tid] = h_b[tid]; }
    if (tid < 90)  { const float v = q_w[tid]; qw2[tid] = make_float2(v, v); ww_s[tid] = w[tid]; }
    if (tid < 80)  fc_s[tid] = fc_w[tid];
    __syncthreads();   // sync1

    // ================= phase B: weight collapse from smem (8 lanes/item) =============
    if (tid < 160) {               // warps 0..4 fully active -> full-mask shuffles OK
        const int item = tid >> 3;     // 0..19 (19 dummy)
        const int l    = tid & 7;
        float acc = 0.f;
        if (item < 18) {
            const int i = item / 9, t = item % 9;
            #pragma unroll
            for (int s = 0; s < 19; s++) {
                const int c = l + 8 * s;
                if (c < 150) acc += rw_s[c] * uni[(c * L_I + i) * 9 + t];
            }
        } else if (item == 18) {
            #pragma unroll
            for (int s = 0; s < 19; s++) {
                const int c = l + 8 * s;
                if (c < 150) acc += rw_s[c] * hb_s[c];
            }
        }
        acc += __shfl_xor_sync(0xFFFFFFFFu, acc, 4);
        acc += __shfl_xor_sync(0xFFFFFFFFu, acc, 2);
        acc += __shfl_xor_sync(0xFFFFFFFFu, acc, 1);
        if (l == 0 && item < 19) weffb[item] = acc;
    }
    const int nz = (tid < 90) ? (ww_s[tid] != 0.f) : 0;
    const int f  = __syncthreads_or(nz);    // sync2: weffb ready + flag uniform

    // ================= phase C: r = conv3x3(input, weff) + beff ======================
    float wr[18];
    #pragma unroll
    for (int j = 0; j < 18; j++) wr[j] = weffb[j];
    const float be = weffb[18];
    for (int e = tid; e < RROWS * IM; e += NTHR) {     // 1152 px
        const int rx = e >> 6, y = e & 63;
        const int gr = gx0 - 1 + rx;
        float acc = be;
        #pragma unroll
        for (int i = 0; i < L_I; i++)
            #pragma unroll
            for (int kh = 0; kh < 3; kh++)
                #pragma unroll
                for (int kw = 0; kw < 3; kw++)
                    acc += in_s[i][rx + kh][y + kw] * wr[i * 9 + kh * 3 + kw];
        r_s[rx * STRIDE + (y + 1)] = (gr >= 0 && gr < IM) ? acc : 0.f;
    }
    if (tid < 36) {   // r_s column halos
        const int rr = tid >> 1, c = (tid & 1) * 65;
        r_s[rr * STRIDE + c] = 0.f;
    }
    __syncthreads();   // sync3

    float* outb = out + (size_t)b * L_Q * NPIX;

    if (!f) {
        // ============== FAST PATH: w == 0 -> q == conv(r, q_w), FFMA2-packed =========
        const int l  = tid & 31;
        const int wq = tid >> 5;        // 0..7
        const int y  = 2 * l;           // even column 0..62: pixel pair (y, y+1)
        const int rA = wq, rB = wq + 8; // two output rows per thread

        ull tA[9], tB[9];
        #pragma unroll
        for (int kh = 0; kh < 3; kh++) {
            float2 lo = *(const float2*)&r_s[(rA + kh) * STRIDE + y];
            float2 hi = *(const float2*)&r_s[(rA + kh) * STRIDE + y + 2];
            tA[kh * 3 + 0] = f2u(lo);
            tA[kh * 3 + 1] = pk2(lo.y, hi.x);
            tA[kh * 3 + 2] = f2u(hi);
            lo = *(const float2*)&r_s[(rB + kh) * STRIDE + y];
            hi = *(const float2*)&r_s[(rB + kh) * STRIDE + y + 2];
            tB[kh * 3 + 0] = f2u(lo);
            tB[kh * 3 + 1] = pk2(lo.y, hi.x);
            tB[kh * 3 + 2] = f2u(hi);
        }
        float* oA = outb + (gx0 + rA) * IM + y;
        float* oB = outb + (gx0 + rB) * IM + y;
        #pragma unroll
        for (int o = 0; o < L_Q; o++) {
            ull aA = 0ULL, aB = 0ULL;
            #pragma unroll
            for (int j = 0; j < 9; j++) {
                const ull wv = f2u(qw2[o * 9 + j]);   // broadcast LDS.64
                aA = ffma2(tA[j], wv, aA);
                aB = ffma2(tB[j], wv, aB);
            }
            *(float2*)(oA + o * NPIX) = u2f(aA);
            *(float2*)(oB + o * NPIX) = u2f(aB);
        }
        // gather + logits + argmax: only the CTA whose rows contain sx
        if (tid == 0) {
            const int sx = sx_[b];
            if (sx >= gx0 && sx < gx0 + TILE) {
                const int sy = sy_[b];
                float qv[L_Q];
                #pragma unroll
                for (int o = 0; o < L_Q; o++) {
                    float a = 0.f;
                    #pragma unroll
                    for (int kh = 0; kh < 3; kh++)
                        #pragma unroll
                        for (int kw = 0; kw < 3; kw++)
                            a += r_s[(sx - gx0 + kh) * STRIDE + sy + kw]
                                 * qw2[o * 9 + kh * 3 + kw].x;
                    qv[o] = a;
                }
                logits_and_argmax(qv, fc_s, out, b);
            }
        }
        return;
    }

    // ================== SLOW PATH: w != 0, full k-iteration (tile 0 only) ============
    if (tile != 0) return;
    {
        const int kk = (kptr != nullptr) ? *kptr : 40;
        const float* inb = in + (size_t)b * L_I * NPIX;

        for (int i = tid; i < IMP * IMP; i += NTHR) {
            g_r[b][i] = 0.f; g_vb[0][b][i] = 0.f; g_vb[1][b][i] = 0.f;
        }
        __syncthreads();

        // full-image r
        for (int e = tid; e < NPIX; e += NTHR) {
            const int x = e >> 6, y = e & 63;
            float acc = be;
            for (int i = 0; i < L_I; i++)
                for (int kh = 0; kh < 3; kh++) {
                    const int ix = x + kh - 1;
                    if (ix < 0 || ix >= IM) continue;
                    for (int kw = 0; kw < 3; kw++) {
                        const int iy = y + kw - 1;
                        if (iy < 0 || iy >= IM) continue;
                        acc += inb[i * NPIX + ix * IM + iy] * wr[i * 9 + kh * 3 + kw];
                    }
                }
            g_r[b][(x + 1) * IMP + y + 1] = acc;
        }
        __syncthreads();

        // qr + v0
        for (int e = tid; e < NPIX; e += NTHR) {
            const int x = e >> 6, y = e & 63;
            float t[9];
            for (int kh = 0; kh < 3; kh++)
                for (int kw = 0; kw < 3; kw++)
                    t[kh * 3 + kw] = g_r[b][(x + kh) * IMP + y + kw];
            float vmax = -CUDART_INF_F;
            for (int o = 0; o < L_Q; o++) {
                float a = 0.f;
                for (int j = 0; j < 9; j++) a += t[j] * qw2[o * 9 + j].x;
                g_qr[b][o][e] = a;
                vmax = fmaxf(vmax, a);
            }
            g_vb[0][b][(x + 1) * IMP + y + 1] = vmax;
        }
        __syncthreads();

        int cur = 0;
        for (int it = 0; it < kk - 1; it++) {
            for (int e = tid; e < NPIX; e += NTHR) {
                const int x = e >> 6, y = e & 63;
                float t[9];
                for (int kh = 0; kh < 3; kh++)
                    for (int kw = 0; kw < 3; kw++)
                        t[kh * 3 + kw] = g_vb[cur][b][(x + kh) * IMP + y + kw];
                float vmax = -CUDART_INF_F;
                for (int o = 0; o < L_Q; o++) {
                    float a = g_qr[b][o][e];
                    for (int j = 0; j < 9; j++) a += t[j] * ww_s[o * 9 + j];
                    vmax = fmaxf(vmax, a);
                }
                g_vb[cur ^ 1][b][(x + 1) * IMP + y + 1] = vmax;
            }
            cur ^= 1;
            __syncthreads();
        }

        // final q = qr + conv(v, w)
        for (int e = tid; e < NPIX; e += NTHR) {
            const int x = e >> 6, y = e & 63;
            float t[9];
            for (int kh = 0; kh < 3; kh++)
                for (int kw = 0; kw < 3; kw++)
                    t[kh * 3 + kw] = g_vb[cur][b][(x + kh) * IMP + y + kw];
            for (int o = 0; o < L_Q; o++) {
                float a = g_qr[b][o][e];
                for (int j = 0; j < 9; j++) a += t[j] * ww_s[o * 9 + j];
                outb[o * NPIX + e] = a;
            }
        }
        __syncthreads();

        if (tid == 0) {
            const int sx = sx_[b], sy = sy_[b];
            float qv[L_Q];
            for (int o = 0; o < L_Q; o++) {
                float a = g_qr[b][o][sx * IM + sy];
                for (int kh = 0; kh < 3; kh++)
                    for (int kw = 0; kw < 3; kw++)
                        a += g_vb[cur][b][(sx + kh) * IMP + sy + kw] * ww_s[o * 9 + kh * 3 + kw];
                qv[o] = a;
            }
            logits_and_argmax(qv, fc_s, out, b);
        }
    }
}

extern "C" void kernel_launch(void* const* d_in, const int* in_sizes, int n_in,
                              void* d_out, int out_size)
{
    // Inputs: input_view, state_x, state_y, [k], h_w, h_b, r_w, q_w, w, fc_w
    int hw_idx = -1;
    for (int i = 0; i < n_in; i++) {
        if (in_sizes[i] == 2700) { hw_idx = i; break; }
    }
    if (hw_idx < 0) hw_idx = 4;

    const float* in_v = (const float*)d_in[0];
    const int*   sx   = (const int*)d_in[1];
    const int*   sy   = (const int*)d_in[2];
    const int*   kptr = (hw_idx == 4) ? (const int*)d_in[3] : nullptr;
    const float* h_w  = (const float*)d_in[hw_idx];
    const float* h_b  = (const float*)d_in[hw_idx + 1];
    const float* r_w  = (const float*)d_in[hw_idx + 2];
    const float* q_w  = (const float*)d_in[hw_idx + 3];
    const float* w    = (const float*)d_in[hw_idx + 4];
    const float* fc_w = (const float*)d_in[hw_idx + 5];
    float* out = (float*)d_out;

    dim3 grid(TILES, B_);
    vin_kernel<<<grid, NTHR>>>(in_v, sx, sy, kptr, h_w, h_b, r_w,
                               q_w, w, fc_w, out);
}